// round 17
// baseline (speedup 1.0000x reference)
#include <cuda_runtime.h>
#include <math.h>

// ---------------- problem constants ----------------
#define T_STEPS 16384
#define HD      1028
#define NT      512          // 16 warps, all compute; warp0 also does the tail
#define NWP     16

// Layer 0: 49 CTAs x 21 units (84 rows = 64 reg + 20 smem)
#define N0  49
#define U0  21
#define R0  84
#define RB0 20
// Layer 1: 94 CTAs x 11 units (44 rows = 32 reg + 12 smem)
#define N1  94
#define U1  11
#define R1  44
#define RB1 12

#define CPW 68               // cols per warp: 16*68 = 1088 >= 1028
#define NIT 17               // float4 iters per chunk
#define CRQ 11               // reg-col float4 iters (44 cols in regs)
#define CRC 44
#define CRP 22               // packed f32x2 pairs in regs (CRC/2)
#define SCC 24               // smem cols per reg-row (68-44)
#define VL  1088             // padded vector length
#define RING 4
#define RREP 4
#define NCTA (N0 + N1)       // 143

// ---- L0 smem offsets (floats) ----
#define HS0   0
#define WA0   1088
#define WB0   (WA0 + NWP*2*32*SCC)     // 25664
#define PART0 (WB0 + NWP*RB0*76)       // 49984  ([2][16][96])
#define SUM0  (PART0 + 2*NWP*96)       // 53056
#define BIAS0 (SUM0 + 96)
#define WIH0  (BIAS0 + 96)
#define END0  (WIH0 + 96)              // 53344
// ---- L1 smem offsets ----
#define HSB   0
#define HSA   1088
#define WAB   2176
#define WAA   (WAB + NWP*32*SCC)       // 14464
#define WBM   (WAA + NWP*32*SCC)       // 26752  ([16][12][148]: B at +0, A at +72)
#define PART1 (WBM + NWP*RB1*148)      // 55168  ([2][16][48])
#define SUM1  (PART1 + 2*NWP*48)       // 56704
#define BIAS1 (SUM1 + 48)
#define END1  (BIAS1 + 48)             // 56800
#define SMEM_BYTES (END1 * 4)          // 227,200 B

typedef unsigned long long u64;

// ---------------- device scratch ----------------
// h broadcast: {fp32 value (lo), u32 epoch (hi)} per element. 8B atomicity
// makes value+epoch always consistent -> poll data directly, zero fences.
__device__ u64 g_ha[RING][RREP][VL];
__device__ u64 g_hb[RING][RREP][VL];
__device__ __align__(16) float g_h2[(long long)T_STEPS * HD];
__device__ unsigned g_cnts[64];   // [0]=cnt0 (L0 consume), [32]=cnt1 (L1 consume)

extern __shared__ float sm[];

__device__ __forceinline__ u64 ldx(const u64* p) {
    u64 v;
    asm volatile("ld.relaxed.gpu.global.b64 %0, [%1];" : "=l"(v) : "l"(p) : "memory");
    return v;
}
__device__ __forceinline__ void stx(u64* p, u64 v) {
    asm volatile("st.relaxed.gpu.global.b64 [%0], %1;" :: "l"(p), "l"(v) : "memory");
}
__device__ __forceinline__ void red_inc(unsigned* p) {
    asm volatile("red.release.gpu.global.add.u32 [%0], %1;" :: "l"(p), "r"(1u) : "memory");
}
__device__ __forceinline__ void poll_ge(unsigned* p, unsigned tgt) {
    unsigned v;
    do {
        asm volatile("ld.relaxed.gpu.global.u32 %0, [%1];" : "=r"(v) : "l"(p) : "memory");
    } while (v < tgt);
}
__device__ __forceinline__ float sigm(float v) { return 1.f / (1.f + expf(-v)); }

// ---- packed fp32x2 FMA (sm_100+ PTX-only; 2 exact fp32 FMAs per instr) ----
__device__ __forceinline__ u64 ffma2(u64 a, u64 b, u64 c) {
    u64 d;
    asm("fma.rn.f32x2 %0, %1, %2, %3;" : "=l"(d) : "l"(a), "l"(b), "l"(c));
    return d;
}
__device__ __forceinline__ u64 pack2(float lo, float hi) {
    return (u64)__float_as_uint(lo) | ((u64)__float_as_uint(hi) << 32);
}
__device__ __forceinline__ float unpack_sum(u64 v) {
    return __uint_as_float((unsigned)v) + __uint_as_float((unsigned)(v >> 32));
}

// Per-warp: spin on own 68-atom chunk until all epochs == ep, then write the
// values (already in regs from the matching load) to smem. Detection == fetch.
__device__ __forceinline__ void stage_chunk(const u64* buf, unsigned ep,
                                            float* dst, int c0, int l)
{
    const int i1 = c0 + l, i2 = c0 + 32 + l, i3 = c0 + 64 + l;
    const bool n1 = i1 < HD, n2 = i2 < HD, n3 = (l < 4) && (i3 < HD);
    u64 v1 = 0, v2 = 0, v3 = 0;
    for (;;) {
        if (n1) v1 = ldx(buf + i1);
        if (n2) v2 = ldx(buf + i2);
        if (n3) v3 = ldx(buf + i3);
        bool ok = (!n1 || (unsigned)(v1 >> 32) == ep)
               && (!n2 || (unsigned)(v2 >> 32) == ep)
               && (!n3 || (unsigned)(v3 >> 32) == ep);
        if (__all_sync(0xffffffffu, ok)) break;
    }
    dst[i1] = n1 ? __uint_as_float((unsigned)v1) : 0.f;
    dst[i2] = n2 ? __uint_as_float((unsigned)v2) : 0.f;
    if (l < 4) dst[i3] = n3 ? __uint_as_float((unsigned)v3) : 0.f;
    __syncwarp();
}

__device__ __forceinline__ u64 packh(float v, unsigned ep) {
    return ((u64)ep << 32) | (u64)__float_as_uint(v);
}

// ================= Layer 0 (49 CTAs) =================
__device__ void run_l0(int cb,
                       const float* __restrict__ w_hh, const float* __restrict__ w_ih,
                       const float* __restrict__ bi,   const float* __restrict__ bh,
                       const float* __restrict__ x)
{
    const int tid = threadIdx.x, w = tid >> 5, l = tid & 31;
    const int c0 = w * CPW;
    const int rep = cb & (RREP - 1);

    u64 wr2[2][CRP];   // packed register weights (rows 0..63, one per lane)
    #pragma unroll
    for (int g = 0; g < 2; ++g) {
        int r = g * 32 + l;
        int gate = r / U0, uu = r - gate * U0;
        int gu = cb * U0 + uu;
        const float* wrow = (gu < HD) ? &w_hh[(long long)(gate * HD + gu) * HD] : nullptr;
        #pragma unroll
        for (int j = 0; j < CRP; ++j) {
            int c = c0 + 2 * j;
            float lo = (wrow && c     < HD) ? wrow[c]     : 0.f;
            float hi = (wrow && c + 1 < HD) ? wrow[c + 1] : 0.f;
            wr2[g][j] = pack2(lo, hi);
        }
        for (int j = CRC; j < CPW; ++j) {
            int c = c0 + j;
            sm[WA0 + ((w * 2 + g) * 32 + l) * SCC + (j - CRC)] =
                (wrow && c < HD) ? wrow[c] : 0.f;
        }
    }
    if (l < RB0) {
        int r = 64 + l;
        int gate = r / U0, uu = r - gate * U0;
        int gu = cb * U0 + uu;
        const float* wrow = (gu < HD) ? &w_hh[(long long)(gate * HD + gu) * HD] : nullptr;
        for (int j = 0; j < CPW; ++j) {
            int c = c0 + j;
            sm[WB0 + (w * RB0 + l) * 76 + j] = (wrow && c < HD) ? wrow[c] : 0.f;
        }
    }
    for (int r = tid; r < R0; r += NT) {
        int gate = r / U0, uu = r - gate * U0;
        int gu = cb * U0 + uu;
        long long row = (long long)gate * HD + gu;
        sm[BIAS0 + r] = (gu < HD) ? bi[row] + bh[row] : 0.f;
        sm[WIH0 + r]  = (gu < HD) ? w_ih[row] : 0.f;
    }
    __syncthreads();

    float creg = 0.f;

    for (int t = 0; t < T_STEPS; ++t) {
        const int p = t & 1;
        stage_chunk(&g_ha[t & 3][rep][0], (unsigned)t, sm + HS0, c0, l);

        u64 p0 = 0, p1 = 0, pb = 0;
        #pragma unroll
        for (int j4 = 0; j4 < NIT; ++j4) {
            ulonglong2 hv = *(const ulonglong2*)&sm[HS0 + c0 + 4 * j4];
            if (j4 < CRQ) {
                p0 = ffma2(wr2[0][2*j4],     hv.x, p0);
                p0 = ffma2(wr2[0][2*j4 + 1], hv.y, p0);
                p1 = ffma2(wr2[1][2*j4],     hv.x, p1);
                p1 = ffma2(wr2[1][2*j4 + 1], hv.y, p1);
            } else {
                ulonglong2 w0 = *(const ulonglong2*)&sm[WA0 + ((w*2+0)*32+l)*SCC + 4*(j4-CRQ)];
                ulonglong2 w1 = *(const ulonglong2*)&sm[WA0 + ((w*2+1)*32+l)*SCC + 4*(j4-CRQ)];
                p0 = ffma2(w0.x, hv.x, p0); p0 = ffma2(w0.y, hv.y, p0);
                p1 = ffma2(w1.x, hv.x, p1); p1 = ffma2(w1.y, hv.y, p1);
            }
            if (l < RB0) {
                ulonglong2 wb = *(const ulonglong2*)&sm[WB0 + (w*RB0+l)*76 + 4*j4];
                pb = ffma2(wb.x, hv.x, pb); pb = ffma2(wb.y, hv.y, pb);
            }
        }
        sm[PART0 + (p*NWP + w)*96 + l]      = unpack_sum(p0);
        sm[PART0 + (p*NWP + w)*96 + 32 + l] = unpack_sum(p1);
        if (l < RB0) sm[PART0 + (p*NWP + w)*96 + 64 + l] = unpack_sum(pb);
        __syncthreads();

        if (w == 0) {
            if (l == 0) {
                red_inc(&g_cnts[0]);   // consumed ha[t]
                if (t >= 3) poll_ge(&g_cnts[0],  (unsigned)(t - 2) * N0);
                if (t >= 4) poll_ge(&g_cnts[32], (unsigned)(t - 3) * N1);
            }
            float xv = 0.f;
            if (l == 0) xv = __ldg(&x[t]);
            xv = __shfl_sync(0xffffffffu, xv, 0);
            #pragma unroll
            for (int slot = 0; slot < 3; ++slot) {
                int rr = slot * 32 + l;
                if (rr < R0) {
                    float s = fmaf(xv, sm[WIH0 + rr], sm[BIAS0 + rr]);
                    #pragma unroll
                    for (int c = 0; c < NWP; ++c) s += sm[PART0 + (p*NWP + c)*96 + rr];
                    sm[SUM0 + rr] = s;
                }
            }
            __syncwarp();
            if (l < U0) {
                int u = cb * U0 + l;
                if (u < HD) {
                    float iv = sigm(sm[SUM0 + l]);
                    float fv = sigm(sm[SUM0 + U0 + l]);
                    float gv = tanhf(sm[SUM0 + 2*U0 + l]);
                    float ov = sigm(sm[SUM0 + 3*U0 + l]);
                    float c2 = fmaf(fv, creg, iv * gv);
                    creg = c2;
                    u64 pk = packh(ov * tanhf(c2), (unsigned)(t + 1));
                    #pragma unroll
                    for (int q = 0; q < RREP; ++q)
                        stx(&g_ha[(t + 1) & 3][q][u], pk);
                }
            }
        }
    }
}

// ================= Layer 1 (94 CTAs) =================
__device__ void run_l1(int cb,
                       const float* __restrict__ w_hh, const float* __restrict__ w_ih,
                       const float* __restrict__ bi,   const float* __restrict__ bh)
{
    const int tid = threadIdx.x, w = tid >> 5, l = tid & 31;
    const int c0 = w * CPW;
    const int rep = cb & (RREP - 1);

    u64 wB2[CRP], wA2[CRP];   // packed register weights (rows 0..31)
    {
        int r = l;
        int gate = r / U1, uu = r - gate * U1;
        int gu = cb * U1 + uu;
        const float* wB_ = (gu < HD) ? &w_hh[(long long)(gate * HD + gu) * HD] : nullptr;
        const float* wA_ = (gu < HD) ? &w_ih[(long long)(gate * HD + gu) * HD] : nullptr;
        #pragma unroll
        for (int j = 0; j < CRP; ++j) {
            int c = c0 + 2 * j;
            float blo = (wB_ && c     < HD) ? wB_[c]     : 0.f;
            float bhi = (wB_ && c + 1 < HD) ? wB_[c + 1] : 0.f;
            float alo = (wA_ && c     < HD) ? wA_[c]     : 0.f;
            float ahi = (wA_ && c + 1 < HD) ? wA_[c + 1] : 0.f;
            wB2[j] = pack2(blo, bhi);
            wA2[j] = pack2(alo, ahi);
        }
        for (int j = CRC; j < CPW; ++j) {
            int c = c0 + j;
            sm[WAB + (w*32+l)*SCC + (j-CRC)] = (wB_ && c < HD) ? wB_[c] : 0.f;
            sm[WAA + (w*32+l)*SCC + (j-CRC)] = (wA_ && c < HD) ? wA_[c] : 0.f;
        }
    }
    if (l < RB1) {
        int r = 32 + l;
        int gate = r / U1, uu = r - gate * U1;
        int gu = cb * U1 + uu;
        const float* wB_ = (gu < HD) ? &w_hh[(long long)(gate * HD + gu) * HD] : nullptr;
        const float* wA_ = (gu < HD) ? &w_ih[(long long)(gate * HD + gu) * HD] : nullptr;
        for (int j = 0; j < CPW; ++j) {
            int c = c0 + j;
            sm[WBM + (w*RB1+l)*148 + j]      = (wB_ && c < HD) ? wB_[c] : 0.f;
            sm[WBM + (w*RB1+l)*148 + 72 + j] = (wA_ && c < HD) ? wA_[c] : 0.f;
        }
    }
    for (int r = tid; r < R1; r += NT) {
        int gate = r / U1, uu = r - gate * U1;
        int gu = cb * U1 + uu;
        long long row = (long long)gate * HD + gu;
        sm[BIAS1 + r] = (gu < HD) ? bi[row] + bh[row] : 0.f;
    }
    __syncthreads();

    float creg = 0.f;

    for (int t = 0; t < T_STEPS; ++t) {
        const int p = t & 1;
        u64 p0 = 0, pb = 0;

        // ---- phase A: ha epoch t+1 (L0 runs ahead -> usually immediate) ----
        stage_chunk(&g_ha[(t + 1) & 3][rep][0], (unsigned)(t + 1), sm + HSA, c0, l);
        #pragma unroll
        for (int j4 = 0; j4 < NIT; ++j4) {
            ulonglong2 hv = *(const ulonglong2*)&sm[HSA + c0 + 4 * j4];
            if (j4 < CRQ) {
                p0 = ffma2(wA2[2*j4],     hv.x, p0);
                p0 = ffma2(wA2[2*j4 + 1], hv.y, p0);
            } else {
                ulonglong2 wv = *(const ulonglong2*)&sm[WAA + (w*32+l)*SCC + 4*(j4-CRQ)];
                p0 = ffma2(wv.x, hv.x, p0); p0 = ffma2(wv.y, hv.y, p0);
            }
            if (l < RB1) {
                ulonglong2 wv = *(const ulonglong2*)&sm[WBM + (w*RB1+l)*148 + 72 + 4*j4];
                pb = ffma2(wv.x, hv.x, pb); pb = ffma2(wv.y, hv.y, pb);
            }
        }

        // ---- phase B: hb epoch t (flight overlapped phase A compute) ----
        stage_chunk(&g_hb[t & 3][rep][0], (unsigned)t, sm + HSB, c0, l);
        #pragma unroll
        for (int j4 = 0; j4 < NIT; ++j4) {
            ulonglong2 hv = *(const ulonglong2*)&sm[HSB + c0 + 4 * j4];
            if (j4 < CRQ) {
                p0 = ffma2(wB2[2*j4],     hv.x, p0);
                p0 = ffma2(wB2[2*j4 + 1], hv.y, p0);
            } else {
                ulonglong2 wv = *(const ulonglong2*)&sm[WAB + (w*32+l)*SCC + 4*(j4-CRQ)];
                p0 = ffma2(wv.x, hv.x, p0); p0 = ffma2(wv.y, hv.y, p0);
            }
            if (l < RB1) {
                ulonglong2 wv = *(const ulonglong2*)&sm[WBM + (w*RB1+l)*148 + 4*j4];
                pb = ffma2(wv.x, hv.x, pb); pb = ffma2(wv.y, hv.y, pb);
            }
        }
        sm[PART1 + (p*NWP + w)*48 + l] = unpack_sum(p0);
        if (l < RB1) sm[PART1 + (p*NWP + w)*48 + 32 + l] = unpack_sum(pb);
        __syncthreads();

        if (w == 0) {
            if (l == 0) {
                red_inc(&g_cnts[32]);  // consumed ha[t+1] + hb[t]
                if (t >= 3) poll_ge(&g_cnts[32], (unsigned)(t - 2) * N1);
            }
            #pragma unroll
            for (int slot = 0; slot < 2; ++slot) {
                int rr = slot * 32 + l;
                if (rr < R1) {
                    float s = sm[BIAS1 + rr];
                    #pragma unroll
                    for (int c = 0; c < NWP; ++c) s += sm[PART1 + (p*NWP + c)*48 + rr];
                    sm[SUM1 + rr] = s;
                }
            }
            __syncwarp();
            if (l < U1) {
                int u = cb * U1 + l;
                if (u < HD) {
                    float iv = sigm(sm[SUM1 + l]);
                    float fv = sigm(sm[SUM1 + U1 + l]);
                    float gv = tanhf(sm[SUM1 + 2*U1 + l]);
                    float ov = sigm(sm[SUM1 + 3*U1 + l]);
                    float c2 = fmaf(fv, creg, iv * gv);
                    creg = c2;
                    float hh = ov * tanhf(c2);
                    u64 pk = packh(hh, (unsigned)(t + 1));
                    #pragma unroll
                    for (int q = 0; q < RREP; ++q)
                        stx(&g_hb[(t + 1) & 3][q][u], pk);
                    g_h2[(long long)t * HD + u] = hh;
                }
            }
        }
    }
}

__global__ void __launch_bounds__(NT, 1) fused_lstm_kernel(
    const float* __restrict__ x,
    const float* __restrict__ w_ih0, const float* __restrict__ w_hh0,
    const float* __restrict__ b_ih0, const float* __restrict__ b_hh0,
    const float* __restrict__ w_ih1, const float* __restrict__ w_hh1,
    const float* __restrict__ b_ih1, const float* __restrict__ b_hh1)
{
    if (blockIdx.x < N0)
        run_l0(blockIdx.x, w_hh0, w_ih0, b_ih0, b_hh0, x);
    else
        run_l1(blockIdx.x - N0, w_hh1, w_ih1, b_ih1, b_hh1);
}

// ---------------- final linear: out[t] = h2[t] . lin_w + lin_b ----------------
__global__ void outdot_kernel(const float* __restrict__ lw,
                              const float* __restrict__ lb,
                              float* __restrict__ out)
{
    const int w = threadIdx.x >> 5;
    const int l = threadIdx.x & 31;
    const int t = blockIdx.x * 4 + w;
    if (t >= T_STEPS) return;
    const float* h = g_h2 + (long long)t * HD;
    float acc = 0.f;
    for (int u = l; u < HD; u += 32) acc = fmaf(h[u], lw[u], acc);
    #pragma unroll
    for (int o = 16; o; o >>= 1) acc += __shfl_down_sync(0xffffffffu, acc, o);
    if (l == 0) out[t] = acc + lb[0];
}

// ---------------- launch ----------------
extern "C" void kernel_launch(void* const* d_in, const int* in_sizes, int n_in,
                              void* d_out, int out_size)
{
    const float* x     = (const float*)d_in[0];
    const float* w_ih0 = (const float*)d_in[1];
    const float* w_hh0 = (const float*)d_in[2];
    const float* b_ih0 = (const float*)d_in[3];
    const float* b_hh0 = (const float*)d_in[4];
    const float* w_ih1 = (const float*)d_in[5];
    const float* w_hh1 = (const float*)d_in[6];
    const float* b_ih1 = (const float*)d_in[7];
    const float* b_hh1 = (const float*)d_in[8];
    const float* lin_w = (const float*)d_in[9];
    const float* lin_b = (const float*)d_in[10];
    float* out = (float*)d_out;

    void *p_ha, *p_hb, *p_cnts;
    cudaGetSymbolAddress(&p_ha,   g_ha);
    cudaGetSymbolAddress(&p_hb,   g_hb);
    cudaGetSymbolAddress(&p_cnts, g_cnts);

    // zero rings (value 0 + epoch 0 == exact initial state) and counters
    cudaMemsetAsync(p_ha,   0, sizeof(u64) * RING * RREP * VL);
    cudaMemsetAsync(p_hb,   0, sizeof(u64) * RING * RREP * VL);
    cudaMemsetAsync(p_cnts, 0, sizeof(unsigned) * 64);

    cudaFuncSetAttribute(fused_lstm_kernel,
                         cudaFuncAttributeMaxDynamicSharedMemorySize, SMEM_BYTES);

    fused_lstm_kernel<<<NCTA, NT, SMEM_BYTES>>>(
        x, w_ih0, w_hh0, b_ih0, b_hh0, w_ih1, w_hh1, b_ih1, b_hh1);

    outdot_kernel<<<(T_STEPS + 3) / 4, 128>>>(lin_w, lin_b, out);
}